// round 12
// baseline (speedup 1.0000x reference)
#include <cuda_runtime.h>
#include <cooperative_groups.h>
#include <cstdint>

namespace cg = cooperative_groups;

#define T_STEPS 2048
#define V_SZ    2048
#define G_SZ    24
#define K_SZ    512
#define CLUSTER_N 8
#define JPB     64              // columns of Wh per CTA
#define NCLUSTERS 12            // 12 clusters * 2 groups * 2 recs = 48
#define NBLOCKS (NCLUSTERS * CLUSTER_N)
#define THREADS_RNN 256

__device__ __forceinline__ void ffma2(unsigned long long& acc,
                                      unsigned long long h2,
                                      unsigned long long w2) {
    asm("fma.rn.f32x2 %0, %1, %2, %0;" : "+l"(acc) : "l"(h2), "l"(w2));
}

__device__ __forceinline__ unsigned long long packf2(float lo, float hi) {
    unsigned long long r;
    asm("mov.b64 %0, {%1, %2};" : "=l"(r) : "f"(lo), "f"(hi));
    return r;
}

__device__ __forceinline__ float sum2(unsigned long long acc) {
    float lo, hi;
    asm("mov.b64 {%0, %1}, %2;" : "=f"(lo), "=f"(hi) : "l"(acc));
    return lo + hi;
}

// Scratch (no cudaMalloc allowed)
__device__ float g_P[V_SZ * K_SZ];       // P = W_e @ Wx + b   (V, K)
__device__ int   g_idx[T_STEPS * G_SZ];  // idx[t,g] = perms[g, token_t]

// L2-resident h exchange: [cid][grp][buf][src][rec*64 + col]
__device__ float g_h[NCLUSTERS][2][2][CLUSTER_N][128];
// publish counters: g_flag[cid][grp][src] = latest step t whose h_t is visible
__device__ int   g_flag[NCLUSTERS][2][CLUSTER_N];

// ---------------------------------------------------------------------------
// Kernel 1 (fused): token recovery + P = W_e @ Wx + b
// ---------------------------------------------------------------------------
__global__ void __launch_bounds__(256)
prep_kernel(const float* __restrict__ seq,
            const int* __restrict__ perms,
            const float* __restrict__ We,
            const float* __restrict__ Wx,
            const float* __restrict__ b) {
    int tid = threadIdx.x;
    int wid = tid >> 5, lane = tid & 31;

    // ---- token part: warp wid scans one one-hot row ----
    {
        int bid = blockIdx.y * gridDim.x + blockIdx.x;   // 0..255
        int row = bid * 8 + wid;                          // 0..2047
        const float4* r4 = (const float4*)(seq + (size_t)row * V_SZ) + lane * 16;
        int found = -1;
        #pragma unroll
        for (int i = 0; i < 16; i++) {
            float4 v = r4[i];
            int base = lane * 64 + i * 4;
            if (v.x > 0.5f) found = base;
            if (v.y > 0.5f) found = base + 1;
            if (v.z > 0.5f) found = base + 2;
            if (v.w > 0.5f) found = base + 3;
        }
        int tok = __reduce_max_sync(0xffffffffu, found);
        if (lane < G_SZ)
            g_idx[row * G_SZ + lane] = perms[lane * V_SZ + tok];
    }

    // ---- GEMM part ----
    __shared__ float sA[64][17];
    __shared__ float sB[16][68];
    int tx = tid & 15, ty = tid >> 4;
    int row0 = blockIdx.y * 64;
    int col0 = blockIdx.x * 64;
    float acc[4][4] = {};

    for (int kc = 0; kc < K_SZ; kc += 16) {
        {
            int v  = tid >> 2;
            int c4 = (tid & 3) * 4;
            float4 av = *(const float4*)&We[(size_t)(row0 + v) * K_SZ + kc + c4];
            sA[v][c4 + 0] = av.x; sA[v][c4 + 1] = av.y;
            sA[v][c4 + 2] = av.z; sA[v][c4 + 3] = av.w;
        }
        {
            int c  = tid >> 4;
            int k4 = (tid & 15) * 4;
            float4 bv = *(const float4*)&Wx[(size_t)(kc + c) * K_SZ + col0 + k4];
            sB[c][k4 + 0] = bv.x; sB[c][k4 + 1] = bv.y;
            sB[c][k4 + 2] = bv.z; sB[c][k4 + 3] = bv.w;
        }
        __syncthreads();
        #pragma unroll
        for (int cc = 0; cc < 16; cc++) {
            float ar[4], br[4];
            #pragma unroll
            for (int u = 0; u < 4; u++) ar[u] = sA[ty * 4 + u][cc];
            #pragma unroll
            for (int ww = 0; ww < 4; ww++) br[ww] = sB[cc][tx * 4 + ww];
            #pragma unroll
            for (int u = 0; u < 4; u++)
                #pragma unroll
                for (int ww = 0; ww < 4; ww++)
                    acc[u][ww] = fmaf(ar[u], br[ww], acc[u][ww]);
        }
        __syncthreads();
    }
    #pragma unroll
    for (int u = 0; u < 4; u++) {
        int r = row0 + ty * 4 + u;
        #pragma unroll
        for (int ww = 0; ww < 4; ww++) {
            int c = col0 + tx * 4 + ww;
            g_P[(size_t)r * K_SZ + c] = acc[u][ww] + b[c];
        }
    }
}

// ---------------------------------------------------------------------------
// Kernel 2: persistent cluster recurrence — R6 structure with the DSMEM bulk
// copy replaced by an L2 broadcast: producers st.global.cg their 512B slice
// and publish with one st.release.gpu flag (monotonic step counter); consumer
// warp w polls only source w's flag (ld.acquire.gpu) and streams the slice
// with __ldcg broadcast loads. No copy engine, no mbarriers.
// ---------------------------------------------------------------------------
__device__ __forceinline__ int tpos(int s, int dir) {
    return dir ? ((s < T_STEPS - 1) ? (T_STEPS - 2 - s) : (T_STEPS - 1)) : s;
}

struct __align__(16) SmemRNN {
    float2 part[8][64];        //  4096 B (bracketed by syncs)
    float2 x2[2][2][64];       //  2048 B [grp][buf][col]
};

__global__ void __launch_bounds__(THREADS_RNN, 1) __cluster_dims__(CLUSTER_N, 1, 1)
rnn_kernel(const float* __restrict__ Wh,
           float* __restrict__ out,
           int writeHt) {
    __shared__ SmemRNN sm;
    cg::cluster_group cluster = cg::this_cluster();
    const int rank = (int)cluster.block_rank();
    const int cid  = blockIdx.x / CLUSTER_N;
    const int tid  = threadIdx.x;
    const int lane = tid & 31;
    const int w    = tid >> 5;          // warp id 0..7 == consumed srcRank
    const int jg   = rank * JPB;

    // ---- weights into registers, packed as f32x2 row-pairs (shared by groups)
    unsigned long long wa2[32], wb2[32];
    {
        const float* base = Wh + (size_t)(w * 64) * K_SZ + jg + lane;
        #pragma unroll
        for (int ii = 0; ii < 32; ii++) {
            wa2[ii] = packf2(base[(size_t)(2 * ii) * K_SZ],
                             base[(size_t)(2 * ii + 1) * K_SZ]);
            wb2[ii] = packf2(base[(size_t)(2 * ii) * K_SZ + 32],
                             base[(size_t)(2 * ii + 1) * K_SZ + 32]);
        }
    }

    // ---- per-launch init: zero our buf0 slices + flags (globals persist!) ----
    if (tid < 128) {
        g_h[cid][0][0][rank][tid] = 0.f;
    } else {
        g_h[cid][1][0][rank][tid - 128] = 0.f;
    }
    if (tid == 0) {
        g_flag[cid][0][rank] = 0;
        g_flag[cid][1][rank] = 0;
    }

    // x for step 0, both groups (fwd: t=0, bwd: t=T-2)
    if (tid < 64) {
        int c = tid;
        #pragma unroll
        for (int g = 0; g < 2; g++) {
            int gg = cid * 2 + g;
            sm.x2[g][0][c] = make_float2(
                g_P[(size_t)g_idx[0 * G_SZ + gg] * K_SZ + jg + c],
                g_P[(size_t)g_idx[(T_STEPS - 2) * G_SZ + gg] * K_SZ + jg + c]);
        }
    }
    // prefetch lanes: lanes 24..31 own column pj; preload idx for s=1
    const bool plane = (lane >= 24);
    const int  pj    = w * 8 + (lane - 24);
    int tF[2], tR[2];
    #pragma unroll
    for (int g = 0; g < 2; g++) {
        int gg = cid * 2 + g;
        tF[g] = g_idx[1 * G_SZ + gg];
        tR[g] = g_idx[(T_STEPS - 3) * G_SZ + gg];
    }
    __threadfence();     // zeros + flags visible at gpu scope
    __syncthreads();
    cluster.sync();      // every CTA in cluster finished init before anyone runs

    const size_t hb0 = (size_t)T_STEPS * G_SZ * 2 * K_SZ;
    int p = 0;
    for (int s = 0; s < T_STEPS; s++) {
        const bool last = (s == T_STEPS - 1);
        const int np = p ^ 1;

        #pragma unroll
        for (int g = 0; g < 2; g++) {
            const int gg = cid * 2 + g;

            // ---- issue x gathers for step s+1 (hidden under mainloop) ----
            float xFn = 0.f, xRn = 0.f;
            if (plane && !last) {
                int xcol2 = jg + pj;
                xFn = g_P[(size_t)tF[g] * K_SZ + xcol2];
                xRn = g_P[(size_t)tR[g] * K_SZ + xcol2];
            }

            // ---- wait only for this warp's source (monotonic flag poll) ----
            if (s > 0 && w != rank) {
                const int* fp = &g_flag[cid][g][w];
                int fv;
                do {
                    asm volatile("ld.acquire.gpu.global.s32 %0, [%1];"
                                 : "=r"(fv) : "l"(fp) : "memory");
                } while (fv < s);
            }

            // ---- phase 1: f32x2 FMAs, h via broadcast __ldcg (L2) ----
            const float4* hb4 = reinterpret_cast<const float4*>(&g_h[cid][g][p][w][0]);
            unsigned long long A0 = 0ull, A1 = 0ull, C0 = 0ull, C1 = 0ull;
            #pragma unroll
            for (int ii = 0; ii < 16; ii++) {
                float4 f0 = __ldcg(hb4 + ii);        // rec0: rows 4ii..4ii+3
                float4 f1 = __ldcg(hb4 + 16 + ii);   // rec1
                ulonglong2 H0 = *reinterpret_cast<ulonglong2*>(&f0);
                ulonglong2 H1 = *reinterpret_cast<ulonglong2*>(&f1);
                ffma2(A0, H0.x, wa2[2 * ii]);  ffma2(A0, H0.y, wa2[2 * ii + 1]);
                ffma2(A1, H1.x, wa2[2 * ii]);  ffma2(A1, H1.y, wa2[2 * ii + 1]);
                ffma2(C0, H0.x, wb2[2 * ii]);  ffma2(C0, H0.y, wb2[2 * ii + 1]);
                ffma2(C1, H1.x, wb2[2 * ii]);  ffma2(C1, H1.y, wb2[2 * ii + 1]);
            }
            sm.part[w][lane]      = make_float2(sum2(A0), sum2(A1));
            sm.part[w][lane + 32] = make_float2(sum2(C0), sum2(C1));
            __syncthreads();

            // ---- phase 2: reduce, tanh, publish h slice to L2 (lanes 0..15) ----
            float va = 0.f;
            const int rrec = lane >> 3;              // 0=fwd, 1=bwd
            const int rcol = w * 8 + (lane & 7);
            if (lane < 16) {
                const float* pf = (const float*)&sm.part[0][0];
                float sa = 0.f;
                #pragma unroll
                for (int q = 0; q < 8; q++)
                    sa += pf[(q * 64 + rcol) * 2 + rrec];
                const float* xf = (const float*)&sm.x2[g][p][0];
                va = tanhf(sa + xf[rcol * 2 + rrec]);
                if (!last)
                    __stcg(&g_h[cid][g][np][rank][rrec * 64 + rcol], va);
            }
            __syncthreads();

            // ---- publish: one release flag store (replaces 7 bulk copies) ----
            if (!last && tid == 0) {
                const int* fp = &g_flag[cid][g][rank];
                asm volatile("st.release.gpu.global.s32 [%0], %1;"
                             :: "l"(fp), "r"(s + 1) : "memory");
            }

            // ---- tail: global out stores + x register rotation ----
            if (lane < 16) {
                int tt = tpos(s, rrec);
                out[((size_t)tt * G_SZ + gg) * (2 * K_SZ) + rrec * K_SZ + jg + rcol] = va;
                if (last && writeHt)
                    out[hb0 + (size_t)gg * (2 * K_SZ) + rrec * K_SZ + jg + rcol] = va;
            } else if (plane && !last) {
                sm.x2[g][np][pj] = make_float2(xFn, xRn);
                if (s + 2 < T_STEPS) {
                    tF[g] = g_idx[tpos(s + 2, 0) * G_SZ + gg];
                    tR[g] = g_idx[tpos(s + 2, 1) * G_SZ + gg];
                }
            }
        }
        p = np;
    }
}

// ---------------------------------------------------------------------------
extern "C" void kernel_launch(void* const* d_in, const int* in_sizes, int n_in,
                              void* d_out, int out_size) {
    const float* seq   = (const float*)d_in[0];  // (T, V)
    const int*   perms = (const int*)  d_in[1];  // (G, V)
    const float* We    = (const float*)d_in[2];  // (V, K)
    const float* Wx    = (const float*)d_in[3];  // (K, K)
    const float* Wh    = (const float*)d_in[4];  // (K, K)
    const float* b     = (const float*)d_in[5];  // (K,)
    float* out = (float*)d_out;
    (void)in_sizes; (void)n_in;

    long long need = (long long)T_STEPS * G_SZ * 2 * K_SZ + (long long)G_SZ * 2 * K_SZ;
    int writeHt = ((long long)out_size >= need) ? 1 : 0;

    dim3 ggrid(K_SZ / 64, V_SZ / 64);   // (8, 32) = 256 blocks
    prep_kernel<<<ggrid, 256>>>(seq, perms, We, Wx, b);
    rnn_kernel<<<NBLOCKS, THREADS_RNN>>>(Wh, out, writeHt);
}

// round 13
// speedup vs baseline: 2.0265x; 2.0265x over previous
#include <cuda_runtime.h>
#include <cooperative_groups.h>
#include <cstdint>

namespace cg = cooperative_groups;

#define T_STEPS 2048
#define V_SZ    2048
#define G_SZ    24
#define K_SZ    512
#define CLUSTER_N 8
#define JPB     64              // columns of Wh per CTA
#define NCLUSTERS 12            // 12 clusters * 2 groups * 2 recs = 48
#define NBLOCKS (NCLUSTERS * CLUSTER_N)
#define THREADS_RNN 256
#define SLICE_B 512             // one CTA's h contribution per group: 2 recs x 64 cols

// ---------------- mbarrier helpers ----------------
#define MBARRIER_INIT(addr, count) \
    asm volatile("mbarrier.init.shared.b64 [%0], %1;" :: "r"((uint32_t)(addr)), "r"((uint32_t)(count)) : "memory")

#define MBARRIER_EXPECT_TX(addr, bytes) \
    asm volatile("mbarrier.arrive.expect_tx.shared.b64 _, [%0], %1;" :: "r"((uint32_t)(addr)), "r"((uint32_t)(bytes)) : "memory")

#define MBARRIER_WAIT_PARITY(mbar_smem_addr, phase_parity) do { \
    uint32_t _mbar = (uint32_t)(mbar_smem_addr); \
    uint32_t _parity = (uint32_t)(phase_parity); \
    uint32_t _done; \
    asm volatile( \
        "{\n\t" \
        ".reg .pred p;\n\t" \
        "mbarrier.try_wait.parity.acquire.cta.shared::cta.b64 p, [%1], %2;\n\t" \
        "selp.b32 %0, 1, 0, p;\n\t" \
        "}" \
        : "=r"(_done) : "r"(_mbar), "r"(_parity) : "memory"); \
    if (!_done) { \
        asm volatile( \
            "{\n\t" \
            ".reg .pred P1;\n\t" \
            "WAIT_LOOP_%=:\n\t" \
            "mbarrier.try_wait.parity.acquire.cta.shared::cta.b64 P1, [%0], %1, 0x989680;\n\t" \
            "@P1 bra.uni WAIT_DONE_%=;\n\t" \
            "bra.uni WAIT_LOOP_%=;\n\t" \
            "WAIT_DONE_%=:\n\t" \
            "}" \
            :: "r"(_mbar), "r"(_parity) : "memory"); \
    } \
} while(0)

__device__ __forceinline__ uint32_t s2u(const void* p) {
    uint32_t a;
    asm("{ .reg .u64 t; cvta.to.shared.u64 t, %1; cvt.u32.u64 %0, t; }" : "=r"(a) : "l"(p));
    return a;
}

__device__ __forceinline__ void ffma2(unsigned long long& acc,
                                      unsigned long long h2,
                                      unsigned long long w2) {
    asm("fma.rn.f32x2 %0, %1, %2, %0;" : "+l"(acc) : "l"(h2), "l"(w2));
}

__device__ __forceinline__ unsigned long long packf2(float lo, float hi) {
    unsigned long long r;
    asm("mov.b64 %0, {%1, %2};" : "=l"(r) : "f"(lo), "f"(hi));
    return r;
}

__device__ __forceinline__ float sum2(unsigned long long acc) {
    float lo, hi;
    asm("mov.b64 {%0, %1}, %2;" : "=f"(lo), "=f"(hi) : "l"(acc));
    return lo + hi;
}

// Scratch (no cudaMalloc allowed)
__device__ float g_P[V_SZ * K_SZ];       // P = W_e @ Wx + b   (V, K)
__device__ int   g_idx[T_STEPS * G_SZ];  // idx[t,g] = perms[g, token_t]
// L2 staging for the h multicast: [cid][grp][buf][src] -> 512B slice
__device__ __align__(16) float g_hx[NCLUSTERS][2][2][CLUSTER_N][128];

// ---------------------------------------------------------------------------
// Kernel 1 (fused): token recovery + P = W_e @ Wx + b
// ---------------------------------------------------------------------------
__global__ void __launch_bounds__(256)
prep_kernel(const float* __restrict__ seq,
            const int* __restrict__ perms,
            const float* __restrict__ We,
            const float* __restrict__ Wx,
            const float* __restrict__ b) {
    int tid = threadIdx.x;
    int wid = tid >> 5, lane = tid & 31;

    // ---- token part: warp wid scans one one-hot row ----
    {
        int bid = blockIdx.y * gridDim.x + blockIdx.x;   // 0..255
        int row = bid * 8 + wid;                          // 0..2047
        const float4* r4 = (const float4*)(seq + (size_t)row * V_SZ) + lane * 16;
        int found = -1;
        #pragma unroll
        for (int i = 0; i < 16; i++) {
            float4 v = r4[i];
            int base = lane * 64 + i * 4;
            if (v.x > 0.5f) found = base;
            if (v.y > 0.5f) found = base + 1;
            if (v.z > 0.5f) found = base + 2;
            if (v.w > 0.5f) found = base + 3;
        }
        int tok = __reduce_max_sync(0xffffffffu, found);
        if (lane < G_SZ)
            g_idx[row * G_SZ + lane] = perms[lane * V_SZ + tok];
    }

    // ---- GEMM part ----
    __shared__ float sA[64][17];
    __shared__ float sB[16][68];
    int tx = tid & 15, ty = tid >> 4;
    int row0 = blockIdx.y * 64;
    int col0 = blockIdx.x * 64;
    float acc[4][4] = {};

    for (int kc = 0; kc < K_SZ; kc += 16) {
        {
            int v  = tid >> 2;
            int c4 = (tid & 3) * 4;
            float4 av = *(const float4*)&We[(size_t)(row0 + v) * K_SZ + kc + c4];
            sA[v][c4 + 0] = av.x; sA[v][c4 + 1] = av.y;
            sA[v][c4 + 2] = av.z; sA[v][c4 + 3] = av.w;
        }
        {
            int c  = tid >> 4;
            int k4 = (tid & 15) * 4;
            float4 bv = *(const float4*)&Wx[(size_t)(kc + c) * K_SZ + col0 + k4];
            sB[c][k4 + 0] = bv.x; sB[c][k4 + 1] = bv.y;
            sB[c][k4 + 2] = bv.z; sB[c][k4 + 3] = bv.w;
        }
        __syncthreads();
        #pragma unroll
        for (int cc = 0; cc < 16; cc++) {
            float ar[4], br[4];
            #pragma unroll
            for (int u = 0; u < 4; u++) ar[u] = sA[ty * 4 + u][cc];
            #pragma unroll
            for (int ww = 0; ww < 4; ww++) br[ww] = sB[cc][tx * 4 + ww];
            #pragma unroll
            for (int u = 0; u < 4; u++)
                #pragma unroll
                for (int ww = 0; ww < 4; ww++)
                    acc[u][ww] = fmaf(ar[u], br[ww], acc[u][ww]);
        }
        __syncthreads();
    }
    #pragma unroll
    for (int u = 0; u < 4; u++) {
        int r = row0 + ty * 4 + u;
        #pragma unroll
        for (int ww = 0; ww < 4; ww++) {
            int c = col0 + tx * 4 + ww;
            g_P[(size_t)r * K_SZ + c] = acc[u][ww] + b[c];
        }
    }
}

// ---------------------------------------------------------------------------
// Kernel 2: persistent cluster recurrence (R6 structure; transport = ONE
// multicast bulk copy per source per slot). Producers stage the 512B h slice
// in L2 (st.global.cg); tid 0 issues cp.async.bulk.shared::cluster.global
// .multicast::cluster (mask 0xFF) delivering slice + complete_tx to the same
// smem/barrier offset in all 8 CTAs. Per-source barriers, count=1, tx=512.
// ---------------------------------------------------------------------------
__device__ __forceinline__ int tpos(int s, int dir) {
    return dir ? ((s < T_STEPS - 1) ? (T_STEPS - 2 - s) : (T_STEPS - 1)) : s;
}

struct __align__(16) SmemRNN {
    float h[2][2][CLUSTER_N][2][64];           // 16384 B [grp][buf][src][rec][col]
    float2 part[8][64];                        //  4096 B (bracketed by syncs)
    float2 x2[2][2][64];                       //  2048 B [grp][buf][col]
    unsigned long long bar[2][2][CLUSTER_N];   //   256 B [grp][buf][src] count=1
};

__global__ void __launch_bounds__(THREADS_RNN, 1) __cluster_dims__(CLUSTER_N, 1, 1)
rnn_kernel(const float* __restrict__ Wh,
           float* __restrict__ out,
           int writeHt) {
    __shared__ SmemRNN sm;
    cg::cluster_group cluster = cg::this_cluster();
    const int rank = (int)cluster.block_rank();
    const int cid  = blockIdx.x / CLUSTER_N;
    const int tid  = threadIdx.x;
    const int lane = tid & 31;
    const int w    = tid >> 5;          // warp id 0..7 == consumed srcRank
    const int jg   = rank * JPB;

    const uint32_t bar_base = s2u(&sm.bar[0][0][0]);
    if (tid < 2 * 2 * CLUSTER_N)
        MBARRIER_INIT(bar_base + tid * 8, 1);   // completes via tx only
    __syncthreads();
    if (tid < 2 * 2 * CLUSTER_N)
        MBARRIER_EXPECT_TX(bar_base + tid * 8, SLICE_B);   // arm phase 0

    // ---- weights into registers, packed as f32x2 row-pairs (shared by groups)
    unsigned long long wa2[32], wb2[32];
    {
        const float* base = Wh + (size_t)(w * 64) * K_SZ + jg + lane;
        #pragma unroll
        for (int ii = 0; ii < 32; ii++) {
            wa2[ii] = packf2(base[(size_t)(2 * ii) * K_SZ],
                             base[(size_t)(2 * ii + 1) * K_SZ]);
            wb2[ii] = packf2(base[(size_t)(2 * ii) * K_SZ + 32],
                             base[(size_t)(2 * ii + 1) * K_SZ + 32]);
        }
    }
    // zero all smem h buffers (step 0 consumes local zeros; no copy needed)
    for (int i = tid; i < 2 * 2 * CLUSTER_N * 2 * 64; i += THREADS_RNN)
        (&sm.h[0][0][0][0][0])[i] = 0.f;
    // x for step 0, both groups (fwd: t=0, bwd: t=T-2)
    if (tid < 64) {
        int c = tid;
        #pragma unroll
        for (int g = 0; g < 2; g++) {
            int gg = cid * 2 + g;
            sm.x2[g][0][c] = make_float2(
                g_P[(size_t)g_idx[0 * G_SZ + gg] * K_SZ + jg + c],
                g_P[(size_t)g_idx[(T_STEPS - 2) * G_SZ + gg] * K_SZ + jg + c]);
        }
    }
    // prefetch lanes: lanes 24..31 own column pj; preload idx for s=1
    const bool plane = (lane >= 24);
    const int  pj    = w * 8 + (lane - 24);
    int tF[2], tR[2];
    #pragma unroll
    for (int g = 0; g < 2; g++) {
        int gg = cid * 2 + g;
        tF[g] = g_idx[1 * G_SZ + gg];
        tR[g] = g_idx[(T_STEPS - 3) * G_SZ + gg];
    }
    __syncthreads();
    cluster.sync();   // barriers armed cluster-wide before any multicast lands

    const uint32_t my_h = s2u(&sm.h[0][0][0][0][0]);
    float* hx_base = &g_hx[cid][0][0][0][0];   // [grp][buf][src][128]

    const size_t hb0 = (size_t)T_STEPS * G_SZ * 2 * K_SZ;
    int p = 0;
    for (int s = 0; s < T_STEPS; s++) {
        const bool last = (s == T_STEPS - 1);
        const int np = p ^ 1;
        const int wpar = ((s >> 1) + 1 - (s & 1)) & 1;

        #pragma unroll
        for (int g = 0; g < 2; g++) {
            const int gg = cid * 2 + g;

            // ---- issue x gathers for step s+1 (hidden under mainloop) ----
            float xFn = 0.f, xRn = 0.f;
            if (plane && !last) {
                int xcol2 = jg + pj;
                xFn = g_P[(size_t)tF[g] * K_SZ + xcol2];
                xRn = g_P[(size_t)tR[g] * K_SZ + xcol2];
            }

            // ---- wait only for this warp's source slice ----
            if (s > 0) {
                uint32_t wb = bar_base + (uint32_t)(((g * 2 + p) * CLUSTER_N + w) * 8);
                MBARRIER_WAIT_PARITY(wb, wpar);
                if (lane == 0) MBARRIER_EXPECT_TX(wb, SLICE_B);   // re-arm
            }

            // ---- phase 1: f32x2 FMAs, h via broadcast LDS.128 ----
            const float* hr0 = &sm.h[g][p][w][0][0];
            const float* hr1 = &sm.h[g][p][w][1][0];
            unsigned long long A0 = 0ull, A1 = 0ull, C0 = 0ull, C1 = 0ull;
            #pragma unroll
            for (int ii = 0; ii < 16; ii++) {
                ulonglong2 H0 = *(const ulonglong2*)(hr0 + 4 * ii);
                ulonglong2 H1 = *(const ulonglong2*)(hr1 + 4 * ii);
                ffma2(A0, H0.x, wa2[2 * ii]);  ffma2(A0, H0.y, wa2[2 * ii + 1]);
                ffma2(A1, H1.x, wa2[2 * ii]);  ffma2(A1, H1.y, wa2[2 * ii + 1]);
                ffma2(C0, H0.x, wb2[2 * ii]);  ffma2(C0, H0.y, wb2[2 * ii + 1]);
                ffma2(C1, H1.x, wb2[2 * ii]);  ffma2(C1, H1.y, wb2[2 * ii + 1]);
            }
            sm.part[w][lane]      = make_float2(sum2(A0), sum2(A1));
            sm.part[w][lane + 32] = make_float2(sum2(C0), sum2(C1));
            __syncthreads();

            // ---- phase 2: reduce, tanh, stage slice in L2 (lanes 0..15) ----
            float va = 0.f;
            const int rrec = lane >> 3;              // 0=fwd, 1=bwd
            const int rcol = w * 8 + (lane & 7);
            if (lane < 16) {
                const float* pf = (const float*)&sm.part[0][0];
                float sa = 0.f;
                #pragma unroll
                for (int q = 0; q < 8; q++)
                    sa += pf[(q * 64 + rcol) * 2 + rrec];
                const float* xf = (const float*)&sm.x2[g][p][0];
                va = tanhf(sa + xf[rcol * 2 + rrec]);
                if (!last)
                    __stcg(hx_base + (((g * 2 + np) * CLUSTER_N + rank) * 128
                                      + rrec * 64 + rcol), va);
            }
            __syncthreads();

            // ---- ONE multicast bulk copy: L2 slice -> all 8 CTAs' smem ----
            if (!last && tid == 0) {
                asm volatile("fence.proxy.async;" ::: "memory");
                uint32_t off  = (uint32_t)(((g * 2 + np) * CLUSTER_N + rank) * SLICE_B);
                uint32_t dst  = my_h + off;
                const float* src = hx_base + ((g * 2 + np) * CLUSTER_N + rank) * 128;
                uint32_t mbar = bar_base + (uint32_t)(((g * 2 + np) * CLUSTER_N + rank) * 8);
                asm volatile(
                    "cp.async.bulk.shared::cluster.global.mbarrier::complete_tx::bytes"
                    ".multicast::cluster [%0], [%1], %2, [%3], %4;"
                    :: "r"(dst), "l"(src), "r"(SLICE_B), "r"(mbar),
                       "h"((unsigned short)0xFF)
                    : "memory");
            }

            // ---- tail: global out stores + x register rotation ----
            if (lane < 16) {
                int tt = tpos(s, rrec);
                out[((size_t)tt * G_SZ + gg) * (2 * K_SZ) + rrec * K_SZ + jg + rcol] = va;
                if (last && writeHt)
                    out[hb0 + (size_t)gg * (2 * K_SZ) + rrec * K_SZ + jg + rcol] = va;
            } else if (plane && !last) {
                sm.x2[g][np][pj] = make_float2(xFn, xRn);
                if (s + 2 < T_STEPS) {
                    tF[g] = g_idx[tpos(s + 2, 0) * G_SZ + gg];
                    tR[g] = g_idx[tpos(s + 2, 1) * G_SZ + gg];
                }
            }
        }
        p = np;
    }
    cluster.sync();   // no CTA exits while peer-bound multicasts may be in flight
}

// ---------------------------------------------------------------------------
extern "C" void kernel_launch(void* const* d_in, const int* in_sizes, int n_in,
                              void* d_out, int out_size) {
    const float* seq   = (const float*)d_in[0];  // (T, V)
    const int*   perms = (const int*)  d_in[1];  // (G, V)
    const float* We    = (const float*)d_in[2];  // (V, K)
    const float* Wx    = (const float*)d_in[3];  // (K, K)
    const float* Wh    = (const float*)d_in[4];  // (K, K)
    const float* b     = (const float*)d_in[5];  // (K,)
    float* out = (float*)d_out;
    (void)in_sizes; (void)n_in;

    long long need = (long long)T_STEPS * G_SZ * 2 * K_SZ + (long long)G_SZ * 2 * K_SZ;
    int writeHt = ((long long)out_size >= need) ? 1 : 0;

    dim3 ggrid(K_SZ / 64, V_SZ / 64);   // (8, 32) = 256 blocks
    prep_kernel<<<ggrid, 256>>>(seq, perms, We, Wx, b);
    rnn_kernel<<<NBLOCKS, THREADS_RNN>>>(Wh, out, writeHt);
}

// round 14
// speedup vs baseline: 2.2060x; 1.0885x over previous
#include <cuda_runtime.h>
#include <cooperative_groups.h>
#include <cstdint>

namespace cg = cooperative_groups;

#define T_STEPS 2048
#define V_SZ    2048
#define G_SZ    24
#define K_SZ    512
#define CLUSTER_N 8
#define JPB     64              // columns of Wh per CTA
#define NCLUSTERS 12            // 12 clusters * 2 groups * 2 recs = 48
#define NBLOCKS (NCLUSTERS * CLUSTER_N)
#define THREADS_RNN 256
#define RPG     2               // recurrences per group (fwd + bwd of one G-group)
#define SLICE_B (RPG * 64 * 4)  // 512 B: one CTA's h contribution per group

// ---------------- mbarrier helpers ----------------
#define MBARRIER_INIT(addr, count) \
    asm volatile("mbarrier.init.shared.b64 [%0], %1;" :: "r"((uint32_t)(addr)), "r"((uint32_t)(count)) : "memory")

#define MBARRIER_EXPECT_TX(addr, bytes) \
    asm volatile("mbarrier.arrive.expect_tx.shared.b64 _, [%0], %1;" :: "r"((uint32_t)(addr)), "r"((uint32_t)(bytes)) : "memory")

#define MBARRIER_WAIT_PARITY(mbar_smem_addr, phase_parity) do { \
    uint32_t _mbar = (uint32_t)(mbar_smem_addr); \
    uint32_t _parity = (uint32_t)(phase_parity); \
    uint32_t _done; \
    asm volatile( \
        "{\n\t" \
        ".reg .pred p;\n\t" \
        "mbarrier.try_wait.parity.acquire.cta.shared::cta.b64 p, [%1], %2;\n\t" \
        "selp.b32 %0, 1, 0, p;\n\t" \
        "}" \
        : "=r"(_done) : "r"(_mbar), "r"(_parity) : "memory"); \
    if (!_done) { \
        asm volatile( \
            "{\n\t" \
            ".reg .pred P1;\n\t" \
            "WAIT_LOOP_%=:\n\t" \
            "mbarrier.try_wait.parity.acquire.cta.shared::cta.b64 P1, [%0], %1, 0x989680;\n\t" \
            "@P1 bra.uni WAIT_DONE_%=;\n\t" \
            "bra.uni WAIT_LOOP_%=;\n\t" \
            "WAIT_DONE_%=:\n\t" \
            "}" \
            :: "r"(_mbar), "r"(_parity) : "memory"); \
    } \
} while(0)

__device__ __forceinline__ uint32_t s2u(const void* p) {
    uint32_t a;
    asm("{ .reg .u64 t; cvta.to.shared.u64 t, %1; cvt.u32.u64 %0, t; }" : "=r"(a) : "l"(p));
    return a;
}

__device__ __forceinline__ void ffma2(unsigned long long& acc,
                                      unsigned long long h2,
                                      unsigned long long w2) {
    asm("fma.rn.f32x2 %0, %1, %2, %0;" : "+l"(acc) : "l"(h2), "l"(w2));
}

__device__ __forceinline__ unsigned long long packf2(float lo, float hi) {
    unsigned long long r;
    asm("mov.b64 %0, {%1, %2};" : "=l"(r) : "f"(lo), "f"(hi));
    return r;
}

__device__ __forceinline__ float sum2(unsigned long long acc) {
    float lo, hi;
    asm("mov.b64 {%0, %1}, %2;" : "=f"(lo), "=f"(hi) : "l"(acc));
    return lo + hi;
}

// fast tanh: 1 - 2/(exp(2x)+1). __expf saturates (inf / 0) so the result
// clamps correctly to +-1. Relative error ~1e-6 — far inside the 1e-3 budget.
__device__ __forceinline__ float fast_tanh(float x) {
    float e = __expf(2.0f * x);
    return 1.0f - __fdividef(2.0f, e + 1.0f);
}

// Scratch (no cudaMalloc allowed)
__device__ float g_P[V_SZ * K_SZ];       // P = W_e @ Wx + b   (V, K)
__device__ int   g_idx[T_STEPS * G_SZ];  // idx[t,g] = perms[g, token_t]

// ---------------------------------------------------------------------------
// Kernel 1 (fused): token recovery + P = W_e @ Wx + b
// ---------------------------------------------------------------------------
__global__ void __launch_bounds__(256)
prep_kernel(const float* __restrict__ seq,
            const int* __restrict__ perms,
            const float* __restrict__ We,
            const float* __restrict__ Wx,
            const float* __restrict__ b) {
    int tid = threadIdx.x;
    int wid = tid >> 5, lane = tid & 31;

    // ---- token part: warp wid scans one one-hot row ----
    {
        int bid = blockIdx.y * gridDim.x + blockIdx.x;   // 0..255
        int row = bid * 8 + wid;                          // 0..2047
        const float4* r4 = (const float4*)(seq + (size_t)row * V_SZ) + lane * 16;
        int found = -1;
        #pragma unroll
        for (int i = 0; i < 16; i++) {
            float4 v = r4[i];
            int base = lane * 64 + i * 4;
            if (v.x > 0.5f) found = base;
            if (v.y > 0.5f) found = base + 1;
            if (v.z > 0.5f) found = base + 2;
            if (v.w > 0.5f) found = base + 3;
        }
        int tok = __reduce_max_sync(0xffffffffu, found);
        if (lane < G_SZ)
            g_idx[row * G_SZ + lane] = perms[lane * V_SZ + tok];
    }

    // ---- GEMM part ----
    __shared__ float sA[64][17];
    __shared__ float sB[16][68];
    int tx = tid & 15, ty = tid >> 4;
    int row0 = blockIdx.y * 64;
    int col0 = blockIdx.x * 64;
    float acc[4][4] = {};

    for (int kc = 0; kc < K_SZ; kc += 16) {
        {
            int v  = tid >> 2;
            int c4 = (tid & 3) * 4;
            float4 av = *(const float4*)&We[(size_t)(row0 + v) * K_SZ + kc + c4];
            sA[v][c4 + 0] = av.x; sA[v][c4 + 1] = av.y;
            sA[v][c4 + 2] = av.z; sA[v][c4 + 3] = av.w;
        }
        {
            int c  = tid >> 4;
            int k4 = (tid & 15) * 4;
            float4 bv = *(const float4*)&Wx[(size_t)(kc + c) * K_SZ + col0 + k4];
            sB[c][k4 + 0] = bv.x; sB[c][k4 + 1] = bv.y;
            sB[c][k4 + 2] = bv.z; sB[c][k4 + 3] = bv.w;
        }
        __syncthreads();
        #pragma unroll
        for (int cc = 0; cc < 16; cc++) {
            float ar[4], br[4];
            #pragma unroll
            for (int u = 0; u < 4; u++) ar[u] = sA[ty * 4 + u][cc];
            #pragma unroll
            for (int ww = 0; ww < 4; ww++) br[ww] = sB[cc][tx * 4 + ww];
            #pragma unroll
            for (int u = 0; u < 4; u++)
                #pragma unroll
                for (int ww = 0; ww < 4; ww++)
                    acc[u][ww] = fmaf(ar[u], br[ww], acc[u][ww]);
        }
        __syncthreads();
    }
    #pragma unroll
    for (int u = 0; u < 4; u++) {
        int r = row0 + ty * 4 + u;
        #pragma unroll
        for (int ww = 0; ww < 4; ww++) {
            int c = col0 + tx * 4 + ww;
            g_P[(size_t)r * K_SZ + c] = acc[u][ww] + b[c];
        }
    }
}

// ---------------------------------------------------------------------------
// Kernel 2: persistent cluster recurrence — R6 (best known) with two cuts:
// fast exp-based tanh and the async-proxy fence hoisted to the issuer threads
// (writes -> __syncthreads -> ONE fence -> bulk-copy issue, canonical pattern).
// ---------------------------------------------------------------------------
__device__ __forceinline__ int tpos(int s, int dir) {
    return dir ? ((s < T_STEPS - 1) ? (T_STEPS - 2 - s) : (T_STEPS - 1)) : s;
}

struct __align__(16) SmemRNN {
    float  h[2][2][CLUSTER_N][RPG][64];        // 16384 B [grp][buf][src][rec][col]
    float2 part[8][64];                        //  4096 B (bracketed by syncs)
    float2 x2[2][2][64];                       //  2048 B [grp][buf][col]
    unsigned long long bar[2][2][CLUSTER_N];   //   256 B [grp][buf][src]
};

__global__ void __launch_bounds__(THREADS_RNN, 1) __cluster_dims__(CLUSTER_N, 1, 1)
rnn_kernel(const float* __restrict__ Wh,
           float* __restrict__ out,
           int writeHt) {
    __shared__ SmemRNN sm;
    cg::cluster_group cluster = cg::this_cluster();
    const int rank = (int)cluster.block_rank();
    const int cid  = blockIdx.x / CLUSTER_N;
    const int tid  = threadIdx.x;
    const int lane = tid & 31;
    const int w    = tid >> 5;          // warp id 0..7 == consumed srcRank
    const int jg   = rank * JPB;

    const uint32_t bar_base = s2u(&sm.bar[0][0][0]);
    if (tid < 2 * 2 * CLUSTER_N)
        MBARRIER_INIT(bar_base + tid * 8, 1);
    __syncthreads();
    // arm both buffers of both groups for this warp's slice (remote only)
    if (lane == 0 && w != rank) {
        #pragma unroll
        for (int gb = 0; gb < 4; gb++)
            MBARRIER_EXPECT_TX(bar_base + (uint32_t)((gb * CLUSTER_N + w) * 8), SLICE_B);
    }

    // ---- weights into registers, packed as f32x2 row-pairs (shared by groups)
    unsigned long long wa2[32], wb2[32];
    {
        const float* base = Wh + (size_t)(w * 64) * K_SZ + jg + lane;
        #pragma unroll
        for (int ii = 0; ii < 32; ii++) {
            wa2[ii] = packf2(base[(size_t)(2 * ii) * K_SZ],
                             base[(size_t)(2 * ii + 1) * K_SZ]);
            wb2[ii] = packf2(base[(size_t)(2 * ii) * K_SZ + 32],
                             base[(size_t)(2 * ii + 1) * K_SZ + 32]);
        }
    }
    // zero all h buffers
    for (int i = tid; i < 2 * 2 * CLUSTER_N * RPG * 64; i += THREADS_RNN)
        (&sm.h[0][0][0][0][0])[i] = 0.f;
    // x for step 0, both groups (fwd: t=0, bwd: t=T-2)
    if (tid < 64) {
        int c = tid;
        #pragma unroll
        for (int g = 0; g < 2; g++) {
            int gg = cid * 2 + g;
            sm.x2[g][0][c] = make_float2(
                g_P[(size_t)g_idx[0 * G_SZ + gg] * K_SZ + jg + c],
                g_P[(size_t)g_idx[(T_STEPS - 2) * G_SZ + gg] * K_SZ + jg + c]);
        }
    }
    // prefetch lanes: lanes 24..31 own column pj; preload idx for s=1
    const bool plane = (lane >= 24);
    const int  pj    = w * 8 + (lane - 24);
    int tF[2], tR[2];
    #pragma unroll
    for (int g = 0; g < 2; g++) {
        int gg = cid * 2 + g;
        tF[g] = g_idx[1 * G_SZ + gg];                 // tpos(1,0)=1
        tR[g] = g_idx[(T_STEPS - 3) * G_SZ + gg];     // tpos(1,1)=T-3
    }
    __syncthreads();
    cluster.sync();   // barriers initialized & armed cluster-wide

    // issuer threads (tid 0..6): destination rank skipping self
    uint32_t rem_h_t = 0, rem_bar_t = 0;
    const uint32_t my_h = s2u(&sm.h[0][0][0][0][0]);
    if (tid < CLUSTER_N - 1) {
        int dst = tid + (tid >= rank ? 1 : 0);
        asm("mapa.shared::cluster.u32 %0, %1, %2;" : "=r"(rem_h_t)   : "r"(my_h),     "r"(dst));
        asm("mapa.shared::cluster.u32 %0, %1, %2;" : "=r"(rem_bar_t) : "r"(bar_base), "r"(dst));
    }

    const size_t hb0 = (size_t)T_STEPS * G_SZ * 2 * K_SZ;
    int p = 0;
    for (int s = 0; s < T_STEPS; s++) {
        const bool last = (s == T_STEPS - 1);
        const int np = p ^ 1;
        // deterministic wait parity for buffer p at step s (s>=1)
        const int wpar = ((s >> 1) + 1 - (s & 1)) & 1;

        #pragma unroll
        for (int g = 0; g < 2; g++) {
            const int gg = cid * 2 + g;

            // ---- prefetch issue for step s+1 (prefetch lanes; latency-hidden)
            float vF = 0.f, vR = 0.f;
            if (plane && !last) {
                vF = g_P[(size_t)tF[g] * K_SZ + jg + pj];
                vR = g_P[(size_t)tR[g] * K_SZ + jg + pj];
            }

            // ---- wait only for this warp's slice (remote only) ----
            if (s > 0 && w != rank) {
                uint32_t wb = bar_base + (uint32_t)(((g * 2 + p) * CLUSTER_N + w) * 8);
                MBARRIER_WAIT_PARITY(wb, wpar);
                if (lane == 0) MBARRIER_EXPECT_TX(wb, SLICE_B);
            }

            // ---- phase 1: f32x2 FMAs, h via broadcast LDS.128 ----
            const float* hr0 = &sm.h[g][p][w][0][0];
            const float* hr1 = &sm.h[g][p][w][1][0];
            unsigned long long A0 = 0ull, A1 = 0ull, C0 = 0ull, C1 = 0ull;
            #pragma unroll
            for (int ii = 0; ii < 16; ii++) {
                ulonglong2 H0 = *(const ulonglong2*)(hr0 + 4 * ii);
                ulonglong2 H1 = *(const ulonglong2*)(hr1 + 4 * ii);
                ffma2(A0, H0.x, wa2[2 * ii]);  ffma2(A0, H0.y, wa2[2 * ii + 1]);
                ffma2(A1, H1.x, wa2[2 * ii]);  ffma2(A1, H1.y, wa2[2 * ii + 1]);
                ffma2(C0, H0.x, wb2[2 * ii]);  ffma2(C0, H0.y, wb2[2 * ii + 1]);
                ffma2(C1, H1.x, wb2[2 * ii]);  ffma2(C1, H1.y, wb2[2 * ii + 1]);
            }
            sm.part[w][lane]      = make_float2(sum2(A0), sum2(A1));
            sm.part[w][lane + 32] = make_float2(sum2(C0), sum2(C1));
            __syncthreads();

            // ---- phase 2: reduce, fast tanh, local h write (lanes 0..15) ----
            float va = 0.f;
            const int rrec = lane >> 3;              // 0=fwd, 1=bwd
            const int rcol = w * 8 + (lane & 7);
            if (lane < 16) {
                const float* pf = (const float*)&sm.part[0][0];
                float sa = 0.f;
                #pragma unroll
                for (int q = 0; q < 8; q++)
                    sa += pf[(q * 64 + rcol) * 2 + rrec];
                const float* xf = (const float*)&sm.x2[g][p][0];
                va = fast_tanh(sa + xf[rcol * 2 + rrec]);
                if (!last)
                    sm.h[g][np][rank][rrec][rcol] = va;
            }
            __syncthreads();

            // ---- 7 consolidated remote copies (512B each); single fence ----
            if (!last && tid < CLUSTER_N - 1) {
                asm volatile("fence.proxy.async.shared::cta;" ::: "memory");
                uint32_t off = (uint32_t)(((g * 2 + np) * CLUSTER_N + rank) * SLICE_B);
                uint32_t rb  = rem_bar_t + (uint32_t)(((g * 2 + np) * CLUSTER_N + rank) * 8);
                asm volatile(
                    "cp.async.bulk.shared::cluster.shared::cta.mbarrier::complete_tx::bytes "
                    "[%0], [%1], %2, [%3];"
                    :: "r"(rem_h_t + off), "r"(my_h + off), "r"(SLICE_B), "r"(rb) : "memory");
            }

            // ---- tail: global out stores + x prefetch store (off critical path)
            if (lane < 16) {
                int tt = tpos(s, rrec);
                out[((size_t)tt * G_SZ + gg) * (2 * K_SZ) + rrec * K_SZ + jg + rcol] = va;
                if (last && writeHt)
                    out[hb0 + (size_t)gg * (2 * K_SZ) + rrec * K_SZ + jg + rcol] = va;
            } else if (plane && !last) {
                sm.x2[g][np][pj] = make_float2(vF, vR);
                int sf = (s + 2 < T_STEPS) ? s + 2 : T_STEPS - 1;
                tF[g] = g_idx[tpos(sf, 0) * G_SZ + gg];
                tR[g] = g_idx[tpos(sf, 1) * G_SZ + gg];
            }
        }
        p = np;
    }
    cluster.sync();   // no CTA exits while peer copies may be in flight
}

// ---------------------------------------------------------------------------
extern "C" void kernel_launch(void* const* d_in, const int* in_sizes, int n_in,
                              void* d_out, int out_size) {
    const float* seq   = (const float*)d_in[0];  // (T, V)
    const int*   perms = (const int*)  d_in[1];  // (G, V)
    const float* We    = (const float*)d_in[2];  // (V, K)
    const float* Wx    = (const float*)d_in[3];  // (K, K)
    const float* Wh    = (const float*)d_in[4];  // (K, K)
    const float* b     = (const float*)d_in[5];  // (K,)
    float* out = (float*)d_out;
    (void)in_sizes; (void)n_in;

    long long need = (long long)T_STEPS * G_SZ * 2 * K_SZ + (long long)G_SZ * 2 * K_SZ;
    int writeHt = ((long long)out_size >= need) ? 1 : 0;

    dim3 ggrid(K_SZ / 64, V_SZ / 64);   // (8, 32) = 256 blocks
    prep_kernel<<<ggrid, 256>>>(seq, perms, We, Wx, b);
    rnn_kernel<<<NBLOCKS, THREADS_RNN>>>(Wh, out, writeHt);
}

// round 15
// speedup vs baseline: 2.3039x; 1.0444x over previous
#include <cuda_runtime.h>
#include <cooperative_groups.h>
#include <cstdint>

namespace cg = cooperative_groups;

#define T_STEPS 2048
#define V_SZ    2048
#define G_SZ    24
#define K_SZ    512
#define CLUSTER_N 8
#define JPB     64              // columns of Wh per CTA
#define NCLUSTERS 12            // 12 clusters * 2 groups * 2 recs = 48
#define NBLOCKS (NCLUSTERS * CLUSTER_N)
#define THREADS_RNN 256
#define RPG     2               // recurrences per group (fwd + bwd of one G-group)
#define SLICE_B (RPG * 64 * 4)  // 512 B: one CTA's h contribution per group

// ---------------- mbarrier helpers ----------------
#define MBARRIER_INIT(addr, count) \
    asm volatile("mbarrier.init.shared.b64 [%0], %1;" :: "r"((uint32_t)(addr)), "r"((uint32_t)(count)) : "memory")

#define MBARRIER_EXPECT_TX(addr, bytes) \
    asm volatile("mbarrier.arrive.expect_tx.shared.b64 _, [%0], %1;" :: "r"((uint32_t)(addr)), "r"((uint32_t)(bytes)) : "memory")

#define MBARRIER_WAIT_PARITY(mbar_smem_addr, phase_parity) do { \
    uint32_t _mbar = (uint32_t)(mbar_smem_addr); \
    uint32_t _parity = (uint32_t)(phase_parity); \
    uint32_t _done; \
    asm volatile( \
        "{\n\t" \
        ".reg .pred p;\n\t" \
        "mbarrier.try_wait.parity.acquire.cta.shared::cta.b64 p, [%1], %2;\n\t" \
        "selp.b32 %0, 1, 0, p;\n\t" \
        "}" \
        : "=r"(_done) : "r"(_mbar), "r"(_parity) : "memory"); \
    if (!_done) { \
        asm volatile( \
            "{\n\t" \
            ".reg .pred P1;\n\t" \
            "WAIT_LOOP_%=:\n\t" \
            "mbarrier.try_wait.parity.acquire.cta.shared::cta.b64 P1, [%0], %1, 0x989680;\n\t" \
            "@P1 bra.uni WAIT_DONE_%=;\n\t" \
            "bra.uni WAIT_LOOP_%=;\n\t" \
            "WAIT_DONE_%=:\n\t" \
            "}" \
            :: "r"(_mbar), "r"(_parity) : "memory"); \
    } \
} while(0)

__device__ __forceinline__ uint32_t s2u(const void* p) {
    uint32_t a;
    asm("{ .reg .u64 t; cvta.to.shared.u64 t, %1; cvt.u32.u64 %0, t; }" : "=r"(a) : "l"(p));
    return a;
}

__device__ __forceinline__ void ffma2(unsigned long long& acc,
                                      unsigned long long h2,
                                      unsigned long long w2) {
    asm("fma.rn.f32x2 %0, %1, %2, %0;" : "+l"(acc) : "l"(h2), "l"(w2));
}

__device__ __forceinline__ unsigned long long packf2(float lo, float hi) {
    unsigned long long r;
    asm("mov.b64 %0, {%1, %2};" : "=l"(r) : "f"(lo), "f"(hi));
    return r;
}

__device__ __forceinline__ float sum2(unsigned long long acc) {
    float lo, hi;
    asm("mov.b64 {%0, %1}, %2;" : "=f"(lo), "=f"(hi) : "l"(acc));
    return lo + hi;
}

// fast tanh: 1 - 2/(exp(2x)+1); __expf saturates so result clamps to +-1.
__device__ __forceinline__ float fast_tanh(float x) {
    float e = __expf(2.0f * x);
    return 1.0f - __fdividef(2.0f, e + 1.0f);
}

// Scratch (no cudaMalloc allowed)
__device__ float g_P[V_SZ * K_SZ];       // P = W_e @ Wx + b   (V, K)
__device__ int   g_idx[T_STEPS * G_SZ];  // idx[t,g] = perms[g, token_t]

// ---------------------------------------------------------------------------
// Kernel 1 (fused): token recovery + P = W_e @ Wx + b
// ---------------------------------------------------------------------------
__global__ void __launch_bounds__(256)
prep_kernel(const float* __restrict__ seq,
            const int* __restrict__ perms,
            const float* __restrict__ We,
            const float* __restrict__ Wx,
            const float* __restrict__ b) {
    int tid = threadIdx.x;
    int wid = tid >> 5, lane = tid & 31;

    // ---- token part: warp wid scans one one-hot row ----
    {
        int bid = blockIdx.y * gridDim.x + blockIdx.x;   // 0..255
        int row = bid * 8 + wid;                          // 0..2047
        const float4* r4 = (const float4*)(seq + (size_t)row * V_SZ) + lane * 16;
        int found = -1;
        #pragma unroll
        for (int i = 0; i < 16; i++) {
            float4 v = r4[i];
            int base = lane * 64 + i * 4;
            if (v.x > 0.5f) found = base;
            if (v.y > 0.5f) found = base + 1;
            if (v.z > 0.5f) found = base + 2;
            if (v.w > 0.5f) found = base + 3;
        }
        int tok = __reduce_max_sync(0xffffffffu, found);
        if (lane < G_SZ)
            g_idx[row * G_SZ + lane] = perms[lane * V_SZ + tok];
    }

    // ---- GEMM part ----
    __shared__ float sA[64][17];
    __shared__ float sB[16][68];
    int tx = tid & 15, ty = tid >> 4;
    int row0 = blockIdx.y * 64;
    int col0 = blockIdx.x * 64;
    float acc[4][4] = {};

    for (int kc = 0; kc < K_SZ; kc += 16) {
        {
            int v  = tid >> 2;
            int c4 = (tid & 3) * 4;
            float4 av = *(const float4*)&We[(size_t)(row0 + v) * K_SZ + kc + c4];
            sA[v][c4 + 0] = av.x; sA[v][c4 + 1] = av.y;
            sA[v][c4 + 2] = av.z; sA[v][c4 + 3] = av.w;
        }
        {
            int c  = tid >> 4;
            int k4 = (tid & 15) * 4;
            float4 bv = *(const float4*)&Wx[(size_t)(kc + c) * K_SZ + col0 + k4];
            sB[c][k4 + 0] = bv.x; sB[c][k4 + 1] = bv.y;
            sB[c][k4 + 2] = bv.z; sB[c][k4 + 3] = bv.w;
        }
        __syncthreads();
        #pragma unroll
        for (int cc = 0; cc < 16; cc++) {
            float ar[4], br[4];
            #pragma unroll
            for (int u = 0; u < 4; u++) ar[u] = sA[ty * 4 + u][cc];
            #pragma unroll
            for (int ww = 0; ww < 4; ww++) br[ww] = sB[cc][tx * 4 + ww];
            #pragma unroll
            for (int u = 0; u < 4; u++)
                #pragma unroll
                for (int ww = 0; ww < 4; ww++)
                    acc[u][ww] = fmaf(ar[u], br[ww], acc[u][ww]);
        }
        __syncthreads();
    }
    #pragma unroll
    for (int u = 0; u < 4; u++) {
        int r = row0 + ty * 4 + u;
        #pragma unroll
        for (int ww = 0; ww < 4; ww++) {
            int c = col0 + tx * 4 + ww;
            g_P[(size_t)r * K_SZ + c] = acc[u][ww] + b[c];
        }
    }
}

// ---------------------------------------------------------------------------
// Kernel 2: persistent cluster recurrence — R6 structure; transport is
// st.async direct remote stores with complete_tx (no copy engine, no fences,
// no second __syncthreads). part[] double-buffered by group closes the
// lapping race via the own-source barrier causality chain.
// ---------------------------------------------------------------------------
__device__ __forceinline__ int tpos(int s, int dir) {
    return dir ? ((s < T_STEPS - 1) ? (T_STEPS - 2 - s) : (T_STEPS - 1)) : s;
}

struct __align__(16) SmemRNN {
    float  h[2][2][CLUSTER_N][RPG][64];        // 16384 B [grp][buf][src][rec][col]
    float2 part[2][8][64];                     //  8192 B [grp][warp][col]
    float2 x2[2][2][64];                       //  2048 B [grp][buf][col]
    unsigned long long bar[2][2][CLUSTER_N];   //   256 B [grp][buf][src]
};

__global__ void __launch_bounds__(THREADS_RNN, 1) __cluster_dims__(CLUSTER_N, 1, 1)
rnn_kernel(const float* __restrict__ Wh,
           float* __restrict__ out,
           int writeHt) {
    __shared__ SmemRNN sm;
    cg::cluster_group cluster = cg::this_cluster();
    const int rank = (int)cluster.block_rank();
    const int cid  = blockIdx.x / CLUSTER_N;
    const int tid  = threadIdx.x;
    const int lane = tid & 31;
    const int w    = tid >> 5;          // warp id 0..7 == consumed srcRank
    const int jg   = rank * JPB;

    const uint32_t bar_base = s2u(&sm.bar[0][0][0]);
    if (tid < 2 * 2 * CLUSTER_N)
        MBARRIER_INIT(bar_base + tid * 8, 1);
    __syncthreads();
    if (tid < 2 * 2 * CLUSTER_N)
        MBARRIER_EXPECT_TX(bar_base + tid * 8, SLICE_B);   // arm phase 0 (all 32)

    // ---- weights into registers, packed as f32x2 row-pairs (shared by groups)
    unsigned long long wa2[32], wb2[32];
    {
        const float* base = Wh + (size_t)(w * 64) * K_SZ + jg + lane;
        #pragma unroll
        for (int ii = 0; ii < 32; ii++) {
            wa2[ii] = packf2(base[(size_t)(2 * ii) * K_SZ],
                             base[(size_t)(2 * ii + 1) * K_SZ]);
            wb2[ii] = packf2(base[(size_t)(2 * ii) * K_SZ + 32],
                             base[(size_t)(2 * ii + 1) * K_SZ + 32]);
        }
    }
    // zero all h buffers
    for (int i = tid; i < 2 * 2 * CLUSTER_N * RPG * 64; i += THREADS_RNN)
        (&sm.h[0][0][0][0][0])[i] = 0.f;
    // x for step 0, both groups (fwd: t=0, bwd: t=T-2)
    if (tid < 64) {
        int c = tid;
        #pragma unroll
        for (int g = 0; g < 2; g++) {
            int gg = cid * 2 + g;
            sm.x2[g][0][c] = make_float2(
                g_P[(size_t)g_idx[0 * G_SZ + gg] * K_SZ + jg + c],
                g_P[(size_t)g_idx[(T_STEPS - 2) * G_SZ + gg] * K_SZ + jg + c]);
        }
    }
    // prefetch lanes: lanes 24..31 own column pj; preload idx for s=1
    const bool plane = (lane >= 24);
    const int  pj    = w * 8 + (lane - 24);
    int tF[2], tR[2];
    #pragma unroll
    for (int g = 0; g < 2; g++) {
        int gg = cid * 2 + g;
        tF[g] = g_idx[1 * G_SZ + gg];
        tR[g] = g_idx[(T_STEPS - 3) * G_SZ + gg];
    }
    __syncthreads();
    cluster.sync();   // barriers initialized & armed cluster-wide

    // remote bases for st.async: dest CTA d's h region and barrier array
    const uint32_t my_h = s2u(&sm.h[0][0][0][0][0]);
    uint32_t rem_h[CLUSTER_N], rem_b[CLUSTER_N];
    #pragma unroll
    for (int d = 0; d < CLUSTER_N; d++) {
        asm("mapa.shared::cluster.u32 %0, %1, %2;" : "=r"(rem_h[d]) : "r"(my_h),     "r"(d));
        asm("mapa.shared::cluster.u32 %0, %1, %2;" : "=r"(rem_b[d]) : "r"(bar_base), "r"(d));
    }

    const size_t hb0 = (size_t)T_STEPS * G_SZ * 2 * K_SZ;
    int p = 0;
    for (int s = 0; s < T_STEPS; s++) {
        const bool last = (s == T_STEPS - 1);
        const int np = p ^ 1;
        const int wpar = ((s >> 1) + 1 - (s & 1)) & 1;

        #pragma unroll
        for (int g = 0; g < 2; g++) {
            const int gg = cid * 2 + g;

            // ---- prefetch issue for step s+1 (latency-hidden) ----
            float vF = 0.f, vR = 0.f;
            if (plane && !last) {
                vF = g_P[(size_t)tF[g] * K_SZ + jg + pj];
                vR = g_P[(size_t)tR[g] * K_SZ + jg + pj];
            }

            // ---- wait only for this warp's source slice (all sources now) ----
            if (s > 0) {
                uint32_t wb = bar_base + (uint32_t)(((g * 2 + p) * CLUSTER_N + w) * 8);
                MBARRIER_WAIT_PARITY(wb, wpar);
                if (lane == 0) MBARRIER_EXPECT_TX(wb, SLICE_B);   // re-arm
            }

            // ---- phase 1: f32x2 FMAs, h via broadcast LDS.128 ----
            const float* hr0 = &sm.h[g][p][w][0][0];
            const float* hr1 = &sm.h[g][p][w][1][0];
            unsigned long long A0 = 0ull, A1 = 0ull, C0 = 0ull, C1 = 0ull;
            #pragma unroll
            for (int ii = 0; ii < 16; ii++) {
                ulonglong2 H0 = *(const ulonglong2*)(hr0 + 4 * ii);
                ulonglong2 H1 = *(const ulonglong2*)(hr1 + 4 * ii);
                ffma2(A0, H0.x, wa2[2 * ii]);  ffma2(A0, H0.y, wa2[2 * ii + 1]);
                ffma2(A1, H1.x, wa2[2 * ii]);  ffma2(A1, H1.y, wa2[2 * ii + 1]);
                ffma2(C0, H0.x, wb2[2 * ii]);  ffma2(C0, H0.y, wb2[2 * ii + 1]);
                ffma2(C1, H1.x, wb2[2 * ii]);  ffma2(C1, H1.y, wb2[2 * ii + 1]);
            }
            sm.part[g][w][lane]      = make_float2(sum2(A0), sum2(A1));
            sm.part[g][w][lane + 32] = make_float2(sum2(C0), sum2(C1));
            __syncthreads();   // the ONLY block sync per slot (reduce dependency)

            // ---- phase 2: reduce, fast tanh, st.async broadcast (lanes 0..15)
            float va = 0.f;
            const int rrec = lane >> 3;              // 0=fwd, 1=bwd
            const int rcol = w * 8 + (lane & 7);
            if (lane < 16) {
                const float* pf = (const float*)&sm.part[g][0][0];
                float sa = 0.f;
                #pragma unroll
                for (int q = 0; q < 8; q++)
                    sa += pf[(q * 64 + rcol) * 2 + rrec];
                const float* xf = (const float*)&sm.x2[g][p][0];
                va = fast_tanh(sa + xf[rcol * 2 + rrec]);
                if (!last) {
                    // direct remote stores with transaction accounting:
                    // each lane sends its 4B to the same offset in all 8 CTAs.
                    uint32_t val  = __float_as_uint(va);
                    uint32_t hoff = (uint32_t)(((g * 2 + np) * CLUSTER_N + rank) * SLICE_B
                                               + (rrec * 64 + rcol) * 4);
                    uint32_t boff = (uint32_t)(((g * 2 + np) * CLUSTER_N + rank) * 8);
                    #pragma unroll
                    for (int d = 0; d < CLUSTER_N; d++) {
                        asm volatile(
                            "st.async.shared::cluster.mbarrier::complete_tx::bytes.b32 "
                            "[%0], %1, [%2];"
                            :: "r"(rem_h[d] + hoff), "r"(val), "r"(rem_b[d] + boff)
                            : "memory");
                    }
                }
            }

            // ---- tail: global out stores + x prefetch store (off critical path)
            if (lane < 16) {
                int tt = tpos(s, rrec);
                out[((size_t)tt * G_SZ + gg) * (2 * K_SZ) + rrec * K_SZ + jg + rcol] = va;
                if (last && writeHt)
                    out[hb0 + (size_t)gg * (2 * K_SZ) + rrec * K_SZ + jg + rcol] = va;
            } else if (plane && !last) {
                sm.x2[g][np][pj] = make_float2(vF, vR);
                int sf = (s + 2 < T_STEPS) ? s + 2 : T_STEPS - 1;
                tF[g] = g_idx[tpos(sf, 0) * G_SZ + gg];
                tR[g] = g_idx[tpos(sf, 1) * G_SZ + gg];
            }
        }
        p = np;
    }
    cluster.sync();   // no CTA exits while peer-bound stores may be in flight
}

// ---------------------------------------------------------------------------
extern "C" void kernel_launch(void* const* d_in, const int* in_sizes, int n_in,
                              void* d_out, int out_size) {
    const float* seq   = (const float*)d_in[0];  // (T, V)
    const int*   perms = (const int*)  d_in[1];  // (G, V)
    const float* We    = (const float*)d_in[2];  // (V, K)
    const float* Wx    = (const float*)d_in[3];  // (K, K)
    const float* Wh    = (const float*)d_in[4];  // (K, K)
    const float* b     = (const float*)d_in[5];  // (K,)
    float* out = (float*)d_out;
    (void)in_sizes; (void)n_in;

    long long need = (long long)T_STEPS * G_SZ * 2 * K_SZ + (long long)G_SZ * 2 * K_SZ;
    int writeHt = ((long long)out_size >= need) ? 1 : 0;

    dim3 ggrid(K_SZ / 64, V_SZ / 64);   // (8, 32) = 256 blocks
    prep_kernel<<<ggrid, 256>>>(seq, perms, We, Wx, b);
    rnn_kernel<<<NBLOCKS, THREADS_RNN>>>(Wh, out, writeHt);
}